// round 2
// baseline (speedup 1.0000x reference)
#include <cuda_runtime.h>
#include <cstddef>

#define BATCH 16384
#define NND   7
#define FEATD 512
#define HID   256
#define CTXD  256
#define MROWS (BATCH * NND)        // 114688
#define GB    8                    // batches per attention block
#define CS    2052                 // padded combined stride (floats), bank-shifted

// ---------------- scratch (no allocs allowed; __device__ globals) ----------
__device__ float g_h1[(size_t)MROWS * HID];   // GEMM1 out (pre-relu h, layer 1)
__device__ float g_x2[(size_t)MROWS * HID];   // relu(alpha1 @ h1)
__device__ float g_h2[(size_t)MROWS * HID];   // GEMM2 out (pre-relu h, layer 2)

// ---------------------------------------------------------------------------
// C[m, n] = sum_k A[m,k] * W[n,k]      (A: MxK row-major, W: NxK row-major)
// Tile 128x128, BK=8, 256 threads, 8x8 per thread, global->smem double buffer.
// M % 128 == 0, N % 128 == 0, K % 8 == 0 guaranteed by problem shapes.
// ---------------------------------------------------------------------------
__global__ void __launch_bounds__(256, 2)
gemm_nt(const float* __restrict__ A, const float* __restrict__ W,
        float* __restrict__ C, int K, int Nout) {
    __shared__ float As[2][8][128];
    __shared__ float Bs[2][8][128];
    const int tid = threadIdx.x;
    const int m0 = blockIdx.x * 128;
    const int n0 = blockIdx.y * 128;
    const int lr = tid >> 1;            // 0..127 tile row
    const int lk = (tid & 1) << 2;      // 0 or 4
    const float* Ap = A + (size_t)(m0 + lr) * K + lk;
    const float* Bp = W + (size_t)(n0 + lr) * K + lk;
    const int tx = tid & 15, ty = tid >> 4;

    float acc[8][8];
#pragma unroll
    for (int i = 0; i < 8; ++i)
#pragma unroll
        for (int j = 0; j < 8; ++j) acc[i][j] = 0.f;

    {
        float4 av = *(const float4*)Ap;
        float4 bv = *(const float4*)Bp;
        As[0][lk + 0][lr] = av.x; As[0][lk + 1][lr] = av.y;
        As[0][lk + 2][lr] = av.z; As[0][lk + 3][lr] = av.w;
        Bs[0][lk + 0][lr] = bv.x; Bs[0][lk + 1][lr] = bv.y;
        Bs[0][lk + 2][lr] = bv.z; Bs[0][lk + 3][lr] = bv.w;
    }
    __syncthreads();

    const int nk = K >> 3;
    for (int kt = 0; kt < nk; ++kt) {
        const int buf = kt & 1;
        float4 a2v, b2v;
        const bool more = (kt + 1 < nk);
        if (more) {
            a2v = *(const float4*)(Ap + (kt + 1) * 8);
            b2v = *(const float4*)(Bp + (kt + 1) * 8);
        }
#pragma unroll
        for (int k = 0; k < 8; ++k) {
            float ar[8], br[8];
            float4 t0 = *(const float4*)&As[buf][k][ty * 4];
            float4 t1 = *(const float4*)&As[buf][k][64 + ty * 4];
            ar[0] = t0.x; ar[1] = t0.y; ar[2] = t0.z; ar[3] = t0.w;
            ar[4] = t1.x; ar[5] = t1.y; ar[6] = t1.z; ar[7] = t1.w;
            float4 u0 = *(const float4*)&Bs[buf][k][tx * 4];
            float4 u1 = *(const float4*)&Bs[buf][k][64 + tx * 4];
            br[0] = u0.x; br[1] = u0.y; br[2] = u0.z; br[3] = u0.w;
            br[4] = u1.x; br[5] = u1.y; br[6] = u1.z; br[7] = u1.w;
#pragma unroll
            for (int i = 0; i < 8; ++i)
#pragma unroll
                for (int j = 0; j < 8; ++j)
                    acc[i][j] = fmaf(ar[i], br[j], acc[i][j]);
        }
        if (more) {
            const int nb = buf ^ 1;
            As[nb][lk + 0][lr] = a2v.x; As[nb][lk + 1][lr] = a2v.y;
            As[nb][lk + 2][lr] = a2v.z; As[nb][lk + 3][lr] = a2v.w;
            Bs[nb][lk + 0][lr] = b2v.x; Bs[nb][lk + 1][lr] = b2v.y;
            Bs[nb][lk + 2][lr] = b2v.z; Bs[nb][lk + 3][lr] = b2v.w;
            __syncthreads();
        }
    }

#pragma unroll
    for (int i = 0; i < 8; ++i) {
        const int m = m0 + ((i < 4) ? (ty * 4 + i) : (64 + ty * 4 + i - 4));
        float* Cr = C + (size_t)m * Nout + n0;
        *(float4*)(Cr + tx * 4)      = make_float4(acc[i][0], acc[i][1], acc[i][2], acc[i][3]);
        *(float4*)(Cr + 64 + tx * 4) = make_float4(acc[i][4], acc[i][5], acc[i][6], acc[i][7]);
    }
}

// ---------------------------------------------------------------------------
// GAT attention layer 1: consumes h1 (pre-relu), writes x2 = relu(alpha @ h1).
// One block handles GB=8 batches (8*7*256 floats of h in smem).
// ---------------------------------------------------------------------------
__global__ void __launch_bounds__(256)
attn1_kernel(const float* __restrict__ h1, const float* __restrict__ adj,
             const float* __restrict__ a1, float* __restrict__ x2) {
    extern __shared__ float sm[];
    float* hs   = sm;           // 14336
    float* av   = sm + 14336;   // 512
    float* sadj = sm + 14848;   // 49
    float* ssi  = sm + 14897;   // 56
    float* ssj  = sm + 14953;   // 56
    float* sal  = sm + 15009;   // 392
    const int tid = threadIdx.x;
    const size_t base = (size_t)blockIdx.x * (GB * NND * HID);

    {
        const float4* src = (const float4*)(h1 + base);
        float4* dst = (float4*)hs;
        for (int i = tid; i < GB * NND * HID / 4; i += 256) dst[i] = src[i];
        if (tid < 128) ((float4*)av)[tid] = ((const float4*)a1)[tid];
        if (tid < 49) sadj[tid] = adj[tid];
    }
    __syncthreads();

    {   // s_i / s_j dots (warp-per-7-rows)
        const int w = tid >> 5, lane = tid & 31;
        for (int r = w * 7; r < w * 7 + 7; ++r) {
            const float* hr = hs + r * HID;
            float si = 0.f, sj = 0.f;
#pragma unroll
            for (int k = lane; k < HID; k += 32) {
                const float hv = hr[k];
                si = fmaf(hv, av[k], si);
                sj = fmaf(hv, av[HID + k], sj);
            }
#pragma unroll
            for (int off = 16; off > 0; off >>= 1) {
                si += __shfl_xor_sync(0xffffffffu, si, off);
                sj += __shfl_xor_sync(0xffffffffu, sj, off);
            }
            if (lane == 0) { ssi[r] = si; ssj[r] = sj; }
        }
    }
    __syncthreads();

    if (tid < GB * NND) {   // softmax rows
        const int b = tid / 7, i = tid - b * 7;
        float e[7]; float mx = -3.0e38f;
#pragma unroll
        for (int j = 0; j < 7; ++j) {
            float v = ssi[b * 7 + i] + ssj[b * 7 + j];
            v = (v > 0.f) ? v : 0.2f * v;
            if (sadj[i * 7 + j] == 0.f) v = -3.0e38f;
            e[j] = v; mx = fmaxf(mx, v);
        }
        float s = 0.f;
#pragma unroll
        for (int j = 0; j < 7; ++j) {
            const float ex = (e[j] < -1.0e38f) ? 0.f : __expf(e[j] - mx);
            e[j] = ex; s += ex;
        }
        const float inv = 1.f / s;
#pragma unroll
        for (int j = 0; j < 7; ++j) sal[tid * 7 + j] = e[j] * inv;
    }
    __syncthreads();

    for (int idx = tid; idx < GB * NND * HID; idx += 256) {
        const int b = idx / (NND * HID);
        const int rem = idx - b * (NND * HID);
        const int i = rem >> 8;
        const int d = rem & 255;
        const float* al = sal + (b * 7 + i) * 7;
        float acc = 0.f;
#pragma unroll
        for (int j = 0; j < 7; ++j) acc = fmaf(al[j], hs[(b * 7 + j) * HID + d], acc);
        x2[base + idx] = fmaxf(acc, 0.f);
    }
}

// ---------------------------------------------------------------------------
// GAT layer 2 attention + all MLP heads, fully fused. Writes pred, weights,
// attn2 into the output buffer:  out = [pred(B) | weights(B*5) | attn2(B*49)]
// ---------------------------------------------------------------------------
__global__ void __launch_bounds__(256)
attn2_heads_kernel(const float* __restrict__ h2, const float* __restrict__ adj,
                   const float* __restrict__ a2, const float* __restrict__ context,
                   const float* __restrict__ base_preds,
                   const float* __restrict__ wh1_w, const float* __restrict__ wh1_b,
                   const float* __restrict__ wh2_w, const float* __restrict__ wh2_b,
                   const float* __restrict__ wh3_w, const float* __restrict__ wh3_b,
                   const float* __restrict__ rh1_w, const float* __restrict__ rh1_b,
                   const float* __restrict__ rh2_w, const float* __restrict__ rh2_b,
                   float* __restrict__ out) {
    extern __shared__ float sm[];
    float* hs   = sm;           // 14336
    float* comb = sm + 14336;   // GB*CS = 16416
    float* av   = sm + 30752;   // 512
    float* sadj = sm + 31264;   // 49
    float* ssi  = sm + 31313;   // 56
    float* ssj  = sm + 31369;   // 56
    float* sal  = sm + 31425;   // 392
    float* t1s  = sm + 31817;   // 256
    float* rrs  = sm + 32073;   // 128  (total 32201 floats)
    const int tid = threadIdx.x;
    const int b0 = blockIdx.x * GB;
    const size_t base = (size_t)blockIdx.x * (GB * NND * HID);

    {
        const float4* src = (const float4*)(h2 + base);
        float4* dst = (float4*)hs;
        for (int i = tid; i < GB * NND * HID / 4; i += 256) dst[i] = src[i];
        if (tid < 128) ((float4*)av)[tid] = ((const float4*)a2)[tid];
        if (tid < 49) sadj[tid] = adj[tid];
    }
    __syncthreads();

    {
        const int w = tid >> 5, lane = tid & 31;
        for (int r = w * 7; r < w * 7 + 7; ++r) {
            const float* hr = hs + r * HID;
            float si = 0.f, sj = 0.f;
#pragma unroll
            for (int k = lane; k < HID; k += 32) {
                const float hv = hr[k];
                si = fmaf(hv, av[k], si);
                sj = fmaf(hv, av[HID + k], sj);
            }
#pragma unroll
            for (int off = 16; off > 0; off >>= 1) {
                si += __shfl_xor_sync(0xffffffffu, si, off);
                sj += __shfl_xor_sync(0xffffffffu, sj, off);
            }
            if (lane == 0) { ssi[r] = si; ssj[r] = sj; }
        }
    }
    __syncthreads();

    if (tid < GB * NND) {
        const int b = tid / 7, i = tid - b * 7;
        float e[7]; float mx = -3.0e38f;
#pragma unroll
        for (int j = 0; j < 7; ++j) {
            float v = ssi[b * 7 + i] + ssj[b * 7 + j];
            v = (v > 0.f) ? v : 0.2f * v;
            if (sadj[i * 7 + j] == 0.f) v = -3.0e38f;
            e[j] = v; mx = fmaxf(mx, v);
        }
        float s = 0.f;
#pragma unroll
        for (int j = 0; j < 7; ++j) {
            const float ex = (e[j] < -1.0e38f) ? 0.f : __expf(e[j] - mx);
            e[j] = ex; s += ex;
        }
        const float inv = 1.f / s;
        float* oa = out + (size_t)6 * BATCH + (size_t)(b0 + b) * 49 + i * 7;
#pragma unroll
        for (int j = 0; j < 7; ++j) {
            const float al = e[j] * inv;
            sal[tid * 7 + j] = al;
            oa[j] = al;                      // attn2 output
        }
    }
    __syncthreads();

    // aggregate + relu -> graph_embed portion of `combined`
    for (int idx = tid; idx < GB * NND * HID; idx += 256) {
        const int b = idx / (NND * HID);
        const int rem = idx - b * (NND * HID);
        const int i = rem >> 8;
        const float* al = sal + (b * 7 + i) * 7;
        const int d = rem & 255;
        float acc = 0.f;
#pragma unroll
        for (int j = 0; j < 7; ++j) acc = fmaf(al[j], hs[(b * 7 + j) * HID + d], acc);
        comb[b * CS + rem] = fmaxf(acc, 0.f);
    }
    // context tail of `combined`
    for (int idx = tid; idx < GB * CTXD; idx += 256) {
        const int b = idx >> 8, c = idx & 255;
        comb[b * CS + NND * HID + c] = context[(size_t)(b0 + b) * CTXD + c];
    }
    __syncthreads();

    {   // weight head layer 1: 32 rows x 8 batches = 256 threads
        const int row = tid >> 3, b = tid & 7;
        const float4* wv = (const float4*)wh1_w + row * 512;
        const float4* cv = (const float4*)(comb + b * CS);
        float4 a4 = make_float4(0.f, 0.f, 0.f, 0.f);
        for (int k = 0; k < 512; ++k) {
            const float4 w4 = wv[k], c4 = cv[k];
            a4.x = fmaf(w4.x, c4.x, a4.x);
            a4.y = fmaf(w4.y, c4.y, a4.y);
            a4.z = fmaf(w4.z, c4.z, a4.z);
            a4.w = fmaf(w4.w, c4.w, a4.w);
        }
        const float s = a4.x + a4.y + a4.z + a4.w + wh1_b[row];
        t1s[b * 32 + row] = fmaxf(s, 0.f);
    }
    if (tid < 128) {   // residual head layer 1: 16 rows x 8 batches
        const int row = tid >> 3, b = tid & 7;
        const float4* wv = (const float4*)rh1_w + row * 512;
        const float4* cv = (const float4*)(comb + b * CS);
        float4 a4 = make_float4(0.f, 0.f, 0.f, 0.f);
        for (int k = 0; k < 512; ++k) {
            const float4 w4 = wv[k], c4 = cv[k];
            a4.x = fmaf(w4.x, c4.x, a4.x);
            a4.y = fmaf(w4.y, c4.y, a4.y);
            a4.z = fmaf(w4.z, c4.z, a4.z);
            a4.w = fmaf(w4.w, c4.w, a4.w);
        }
        rrs[b * 16 + row] = tanhf(a4.x + a4.y + a4.z + a4.w + rh1_b[row]);
    }
    __syncthreads();

    if (tid < GB) {   // tiny tail layers, one thread per batch
        const int b = tid;
        float t2[16];
#pragma unroll
        for (int o = 0; o < 16; ++o) {
            float s = wh2_b[o];
#pragma unroll
            for (int k = 0; k < 32; ++k) s = fmaf(t1s[b * 32 + k], wh2_w[o * 32 + k], s);
            t2[o] = fmaxf(s, 0.f);
        }
        float raw[5]; float mx = -3.0e38f;
#pragma unroll
        for (int o = 0; o < 5; ++o) {
            float s = wh3_b[o];
#pragma unroll
            for (int k = 0; k < 16; ++k) s = fmaf(t2[k], wh3_w[o * 16 + k], s);
            raw[o] = s; mx = fmaxf(mx, s);
        }
        float se = 0.f;
#pragma unroll
        for (int o = 0; o < 5; ++o) { raw[o] = __expf(raw[o] - mx); se += raw[o]; }
        const float inv = 1.f / se;
        float wp = 0.f;
#pragma unroll
        for (int o = 0; o < 5; ++o) {
            const float wt = raw[o] * inv;
            out[BATCH + (size_t)(b0 + b) * 5 + o] = wt;     // weights output
            wp = fmaf(wt, base_preds[(size_t)(b0 + b) * 5 + o], wp);
        }
        float rr = rh2_b[0];
#pragma unroll
        for (int k = 0; k < 16; ++k) rr = fmaf(rrs[b * 16 + k], rh2_w[k], rr);
        out[b0 + b] = fmaxf(wp + rr * 0.05f, 0.05f);        // pred output
    }
}

// ---------------------------------------------------------------------------
extern "C" void kernel_launch(void* const* d_in, const int* in_sizes, int n_in,
                              void* d_out, int out_size) {
    const float* node_feats = (const float*)d_in[0];
    const float* adj        = (const float*)d_in[1];
    const float* context    = (const float*)d_in[2];
    const float* base_preds = (const float*)d_in[3];
    const float* W1    = (const float*)d_in[4];
    const float* a1    = (const float*)d_in[5];
    const float* W2    = (const float*)d_in[6];
    const float* a2    = (const float*)d_in[7];
    const float* wh1_w = (const float*)d_in[8];
    const float* wh1_b = (const float*)d_in[9];
    const float* wh2_w = (const float*)d_in[10];
    const float* wh2_b = (const float*)d_in[11];
    const float* wh3_w = (const float*)d_in[12];
    const float* wh3_b = (const float*)d_in[13];
    const float* rh1_w = (const float*)d_in[14];
    const float* rh1_b = (const float*)d_in[15];
    const float* rh2_w = (const float*)d_in[16];
    const float* rh2_b = (const float*)d_in[17];
    float* out = (float*)d_out;

    float *h1p, *x2p, *h2p;
    cudaGetSymbolAddress((void**)&h1p, g_h1);
    cudaGetSymbolAddress((void**)&x2p, g_x2);
    cudaGetSymbolAddress((void**)&h2p, g_h2);

    const int smem1 = 15401 * 4;   // attn1 dynamic smem bytes
    const int smem2 = 32201 * 4;   // attn2+heads dynamic smem bytes
    cudaFuncSetAttribute(attn1_kernel, cudaFuncAttributeMaxDynamicSharedMemorySize, smem1);
    cudaFuncSetAttribute(attn2_heads_kernel, cudaFuncAttributeMaxDynamicSharedMemorySize, smem2);

    // h1 = node_feats @ W1^T
    gemm_nt<<<dim3(MROWS / 128, HID / 128), 256>>>(node_feats, W1, h1p, FEATD, HID);
    // x2 = relu(softmax(mask(lrelu(si+sj))) @ h1)
    attn1_kernel<<<BATCH / GB, 256, smem1>>>(h1p, adj, a1, x2p);
    // h2 = x2 @ W2^T
    gemm_nt<<<dim3(MROWS / 128, HID / 128), 256>>>(x2p, W2, h2p, HID, HID);
    // layer-2 attention + heads + all outputs
    attn2_heads_kernel<<<BATCH / GB, 256, smem2>>>(h2p, adj, a2, context, base_preds,
                                                   wh1_w, wh1_b, wh2_w, wh2_b,
                                                   wh3_w, wh3_b, rh1_w, rh1_b,
                                                   rh2_w, rh2_b, out);
}

// round 4
// speedup vs baseline: 1.7314x; 1.7314x over previous
#include <cuda_runtime.h>
#include <cuda_bf16.h>
#include <cstdint>
#include <cstddef>

#define BATCH 16384
#define NND   7
#define FEATD 512
#define HID   256
#define CTXD  256
#define MROWS (BATCH * NND)        // 114688
#define GB    8                    // batches per attn1 block
#define GB2   4                    // batches per attn2 block
#define CS    2052                 // padded combined stride (floats)

// smem staging layout for mma GEMM (bytes); row stride 80 = 5x16B -> LDSM
// row fetches for 8 consecutive rows land on 8 distinct 16B chunks (mod 128).
#define STR     80
#define AH_OFF  0
#define AL_OFF  10240
#define BH_OFF  20480
#define BL_OFF  30720
#define STAGE   40960
#define G_SMEM  (2 * STAGE)

// ---------------- scratch (no allocs allowed; __device__ globals) ----------
__device__ float g_h1[(size_t)MROWS * HID];
__device__ float g_x2[(size_t)MROWS * HID];
__device__ float g_h2[(size_t)MROWS * HID];
__device__ __nv_bfloat16 g_w1hi[HID * FEATD], g_w1lo[HID * FEATD];
__device__ __nv_bfloat16 g_w2hi[HID * HID],  g_w2lo[HID * HID];

// ---------------- helpers --------------------------------------------------
__device__ __forceinline__ uint32_t smem_u32(const void* p) {
    uint32_t a;
    asm("{ .reg .u64 t; cvta.to.shared.u64 t, %1; cvt.u32.u64 %0, t; }" : "=r"(a) : "l"(p));
    return a;
}
__device__ __forceinline__ void ldsm4(uint32_t* r, uint32_t addr) {
    asm volatile("ldmatrix.sync.aligned.m8n8.x4.shared.b16 {%0,%1,%2,%3}, [%4];"
                 : "=r"(r[0]), "=r"(r[1]), "=r"(r[2]), "=r"(r[3]) : "r"(addr));
}
__device__ __forceinline__ void mma_bf16(float* c, const uint32_t* a, const uint32_t* b) {
    asm volatile(
        "mma.sync.aligned.m16n8k16.row.col.f32.bf16.bf16.f32 "
        "{%0,%1,%2,%3}, {%4,%5,%6,%7}, {%8,%9}, {%0,%1,%2,%3};"
        : "+f"(c[0]), "+f"(c[1]), "+f"(c[2]), "+f"(c[3])
        : "r"(a[0]), "r"(a[1]), "r"(a[2]), "r"(a[3]), "r"(b[0]), "r"(b[1]));
}
__device__ __forceinline__ void cvt_hilo(float4 v, uint32_t& h0, uint32_t& h1,
                                         uint32_t& l0, uint32_t& l1) {
    __nv_bfloat162 ha = __float22bfloat162_rn(make_float2(v.x, v.y));
    __nv_bfloat162 hb = __float22bfloat162_rn(make_float2(v.z, v.w));
    float2 fa = __bfloat1622float2(ha);
    float2 fb = __bfloat1622float2(hb);
    __nv_bfloat162 la = __float22bfloat162_rn(make_float2(v.x - fa.x, v.y - fa.y));
    __nv_bfloat162 lb = __float22bfloat162_rn(make_float2(v.z - fb.x, v.w - fb.y));
    h0 = *(uint32_t*)&ha; h1 = *(uint32_t*)&hb;
    l0 = *(uint32_t*)&la; l1 = *(uint32_t*)&lb;
}

// ---------------------------------------------------------------------------
// Weight pre-split: fp32 -> bf16 hi + bf16 lo(residual)
// ---------------------------------------------------------------------------
__global__ void convw_kernel(const float* __restrict__ W, __nv_bfloat16* __restrict__ hi,
                             __nv_bfloat16* __restrict__ lo, int n) {
    int i = blockIdx.x * 256 + threadIdx.x;
    if (i < n) {
        float x = W[i];
        __nv_bfloat16 h = __float2bfloat16(x);
        hi[i] = h;
        lo[i] = __float2bfloat16(x - __bfloat162float(h));
    }
}

// ---------------------------------------------------------------------------
// HMMA GEMM: C[m,n] = sum_k A[m,k]*W[n,k].  A fp32 (M x K), W pre-split bf16
// hi/lo (256 x K). 3-term split: Ah*Bh + Ah*Bl + Al*Bh.
// Block 128x128, BK=32, 256 threads = 8 warps (4 m x 2 n), warp tile 32x64.
// ---------------------------------------------------------------------------
__global__ void __launch_bounds__(256, 1)
gemm_mma(const float* __restrict__ A, const __nv_bfloat16* __restrict__ Bhi,
         const __nv_bfloat16* __restrict__ Blo, float* __restrict__ C, int K) {
    extern __shared__ char smem[];
    const uint32_t sb = smem_u32(smem);
    const int tid  = threadIdx.x;
    const int lane = tid & 31;
    const int wid  = tid >> 5;
    const int wm   = wid & 3;      // warp row block (32 rows)
    const int wn   = wid >> 2;     // warp col block (64 cols)
    const int m0   = blockIdx.x * 128;
    const int n0   = blockIdx.y * 128;
    const int nk   = K >> 5;       // BK = 32

    // --- staging maps ---
    const int ra = tid >> 1;                 // A row 0..127
    const int ca = (tid & 1) * 16;           // A col base (fp32 within 32-chunk)
    const float* Ag = A + (size_t)(m0 + ra) * K + ca;
    const int rb = tid >> 1;                 // B row 0..127
    const int cb = (tid & 1) * 2;            // B 16B chunk base (0 or 2)
    const char* Bhg = (const char*)Bhi + (size_t)(n0 + rb) * K * 2;
    const char* Blg = (const char*)Blo + (size_t)(n0 + rb) * K * 2;
    char* sA  = smem + AH_OFF + ra * STR + ca * 2;
    char* sAl = smem + AL_OFF + ra * STR + ca * 2;
    char* sBh = smem + BH_OFF + rb * STR + cb * 16;
    char* sBl = smem + BL_OFF + rb * STR + cb * 16;

    // --- LDSM address bases (per warp lane) ---
    const uint32_t a_off = AH_OFF + (uint32_t)(wm * 32 + (lane & 15)) * STR + ((lane >> 4) << 4);
    const uint32_t b_off = BH_OFF + (uint32_t)(wn * 64 + (lane & 7) + ((lane >> 4) << 3)) * STR
                         + ((lane & 8) << 1);

    float acc[2][8][4];
#pragma unroll
    for (int i = 0; i < 2; ++i)
#pragma unroll
        for (int j = 0; j < 8; ++j)
#pragma unroll
            for (int q = 0; q < 4; ++q) acc[i][j][q] = 0.f;

    float4 av[4];
    uint4  bhv[2], blv[2];

    // prologue: load + stage chunk 0
#pragma unroll
    for (int i = 0; i < 4; ++i) av[i] = *(const float4*)(Ag + i * 4);
#pragma unroll
    for (int j = 0; j < 2; ++j) {
        bhv[j] = *(const uint4*)(Bhg + (cb + j) * 16);
        blv[j] = *(const uint4*)(Blg + (cb + j) * 16);
    }
#pragma unroll
    for (int i = 0; i < 4; ++i) {
        uint32_t h0, h1, l0, l1;
        cvt_hilo(av[i], h0, h1, l0, l1);
        *(uint2*)(sA  + i * 8) = make_uint2(h0, h1);
        *(uint2*)(sAl + i * 8) = make_uint2(l0, l1);
    }
#pragma unroll
    for (int j = 0; j < 2; ++j) {
        *(uint4*)(sBh + j * 16) = bhv[j];
        *(uint4*)(sBl + j * 16) = blv[j];
    }
    __syncthreads();

    for (int kt = 0; kt < nk; ++kt) {
        const uint32_t bufo = (kt & 1) * STAGE;
        const bool more = (kt + 1 < nk);
        if (more) {
#pragma unroll
            for (int i = 0; i < 4; ++i) av[i] = *(const float4*)(Ag + (kt + 1) * 32 + i * 4);
#pragma unroll
            for (int j = 0; j < 2; ++j) {
                bhv[j] = *(const uint4*)(Bhg + (kt + 1) * 64 + (cb + j) * 16);
                blv[j] = *(const uint4*)(Blg + (kt + 1) * 64 + (cb + j) * 16);
            }
        }

        // ---- compute BK=32 from buffer bufo ----
#pragma unroll
        for (int ks = 0; ks < 2; ++ks) {
            const uint32_t ab = sb + bufo + a_off + ks * 32;
            const uint32_t bb = sb + bufo + b_off + ks * 32;
            uint32_t ah[2][4], al[2][4];
            ldsm4(ah[0], ab);
            ldsm4(ah[1], ab + 16 * STR);
            ldsm4(al[0], ab + (AL_OFF - AH_OFF));
            ldsm4(al[1], ab + (AL_OFF - AH_OFF) + 16 * STR);
#pragma unroll
            for (int p = 0; p < 4; ++p) {           // n-tile pairs
                uint32_t bh[4], bl[4];
                ldsm4(bh, bb + p * (16 * STR));
                ldsm4(bl, bb + p * (16 * STR) + (BL_OFF - BH_OFF));
#pragma unroll
                for (int mi = 0; mi < 2; ++mi) {
                    mma_bf16(acc[mi][2 * p],     ah[mi], bh);
                    mma_bf16(acc[mi][2 * p],     al[mi], bh);
                    mma_bf16(acc[mi][2 * p],     ah[mi], bl);
                    mma_bf16(acc[mi][2 * p + 1], ah[mi], bh + 2);
                    mma_bf16(acc[mi][2 * p + 1], al[mi], bh + 2);
                    mma_bf16(acc[mi][2 * p + 1], ah[mi], bl + 2);
                }
            }
        }

        if (more) {
            char* dA  = smem + ((kt + 1) & 1) * STAGE;
#pragma unroll
            for (int i = 0; i < 4; ++i) {
                uint32_t h0, h1, l0, l1;
                cvt_hilo(av[i], h0, h1, l0, l1);
                *(uint2*)(dA + AH_OFF + ra * STR + ca * 2 + i * 8) = make_uint2(h0, h1);
                *(uint2*)(dA + AL_OFF + ra * STR + ca * 2 + i * 8) = make_uint2(l0, l1);
            }
#pragma unroll
            for (int j = 0; j < 2; ++j) {
                *(uint4*)(dA + BH_OFF + rb * STR + (cb + j) * 16) = bhv[j];
                *(uint4*)(dA + BL_OFF + rb * STR + (cb + j) * 16) = blv[j];
            }
            __syncthreads();
        }
    }

    // ---- epilogue ----
    const int g  = lane >> 2;
    const int cq = (lane & 3) * 2;
#pragma unroll
    for (int mi = 0; mi < 2; ++mi) {
        const int row0 = m0 + wm * 32 + mi * 16 + g;
        float* C0 = C + (size_t)row0 * 256 + n0 + wn * 64;
        float* C1 = C0 + (size_t)8 * 256;
#pragma unroll
        for (int ni = 0; ni < 8; ++ni) {
            *(float2*)(C0 + ni * 8 + cq) = make_float2(acc[mi][ni][0], acc[mi][ni][1]);
            *(float2*)(C1 + ni * 8 + cq) = make_float2(acc[mi][ni][2], acc[mi][ni][3]);
        }
    }
}

// ---------------------------------------------------------------------------
// GAT attention layer 1: x2 = relu(alpha1 @ h1). 8 batches / block.
// ---------------------------------------------------------------------------
__global__ void __launch_bounds__(256)
attn1_kernel(const float* __restrict__ h1, const float* __restrict__ adj,
             const float* __restrict__ a1, float* __restrict__ x2) {
    extern __shared__ float sm[];
    float* hs   = sm;           // 14336
    float* av   = sm + 14336;   // 512
    float* sadj = sm + 14848;   // 49
    float* ssi  = sm + 14897;   // 56
    float* ssj  = sm + 14953;   // 56
    float* sal  = sm + 15009;   // 392
    const int tid = threadIdx.x;
    const size_t base = (size_t)blockIdx.x * (GB * NND * HID);

    {
        const float4* src = (const float4*)(h1 + base);
        float4* dst = (float4*)hs;
        for (int i = tid; i < GB * NND * HID / 4; i += 256) dst[i] = src[i];
        if (tid < 128) ((float4*)av)[tid] = ((const float4*)a1)[tid];
        if (tid < 49) sadj[tid] = adj[tid];
    }
    __syncthreads();

    {
        const int w = tid >> 5, lane = tid & 31;
        for (int r = w * 7; r < w * 7 + 7; ++r) {
            const float* hr = hs + r * HID;
            float si = 0.f, sj = 0.f;
#pragma unroll
            for (int k = lane; k < HID; k += 32) {
                const float hv = hr[k];
                si = fmaf(hv, av[k], si);
                sj = fmaf(hv, av[HID + k], sj);
            }
#pragma unroll
            for (int off = 16; off > 0; off >>= 1) {
                si += __shfl_xor_sync(0xffffffffu, si, off);
                sj += __shfl_xor_sync(0xffffffffu, sj, off);
            }
            if (lane == 0) { ssi[r] = si; ssj[r] = sj; }
        }
    }
    __syncthreads();

    if (tid < GB * NND) {
        const int b = tid / 7, i = tid - b * 7;
        float e[7]; float mx = -3.0e38f;
#pragma unroll
        for (int j = 0; j < 7; ++j) {
            float v = ssi[b * 7 + i] + ssj[b * 7 + j];
            v = (v > 0.f) ? v : 0.2f * v;
            if (sadj[i * 7 + j] == 0.f) v = -3.0e38f;
            e[j] = v; mx = fmaxf(mx, v);
        }
        float s = 0.f;
#pragma unroll
        for (int j = 0; j < 7; ++j) {
            const float ex = (e[j] < -1.0e38f) ? 0.f : __expf(e[j] - mx);
            e[j] = ex; s += ex;
        }
        const float inv = 1.f / s;
#pragma unroll
        for (int j = 0; j < 7; ++j) sal[tid * 7 + j] = e[j] * inv;
    }
    __syncthreads();

    for (int idx = tid; idx < GB * NND * HID; idx += 256) {
        const int b = idx / (NND * HID);
        const int rem = idx - b * (NND * HID);
        const int i = rem >> 8;
        const int d = rem & 255;
        const float* al = sal + (b * 7 + i) * 7;
        float acc = 0.f;
#pragma unroll
        for (int j = 0; j < 7; ++j) acc = fmaf(al[j], hs[(b * 7 + j) * HID + d], acc);
        x2[base + idx] = fmaxf(acc, 0.f);
    }
}

// ---------------------------------------------------------------------------
// GAT layer 2 attention + MLP heads, fused. GB2=4 batches/block.
// out = [pred(B) | weights(B*5) | attn2(B*49)]
// ---------------------------------------------------------------------------
__global__ void __launch_bounds__(256)
attn2_heads_kernel(const float* __restrict__ h2, const float* __restrict__ adj,
                   const float* __restrict__ a2, const float* __restrict__ context,
                   const float* __restrict__ base_preds,
                   const float* __restrict__ wh1_w, const float* __restrict__ wh1_b,
                   const float* __restrict__ wh2_w, const float* __restrict__ wh2_b,
                   const float* __restrict__ wh3_w, const float* __restrict__ wh3_b,
                   const float* __restrict__ rh1_w, const float* __restrict__ rh1_b,
                   const float* __restrict__ rh2_w, const float* __restrict__ rh2_b,
                   float* __restrict__ out) {
    extern __shared__ float sm[];
    float* hs   = sm;            // 7168
    float* comb = sm + 7168;     // 4*2052 = 8208
    float* av   = sm + 15376;    // 512
    float* sadj = sm + 15888;    // 49
    float* ssi  = sm + 15937;    // 28
    float* ssj  = sm + 15965;    // 28
    float* sal  = sm + 15993;    // 196
    float* t1s  = sm + 16189;    // 128
    float* rrs  = sm + 16317;    // 64   (total 16381 floats)
    const int tid = threadIdx.x;
    const int b0 = blockIdx.x * GB2;
    const size_t base = (size_t)blockIdx.x * (GB2 * NND * HID);

    {
        const float4* src = (const float4*)(h2 + base);
        float4* dst = (float4*)hs;
        for (int i = tid; i < GB2 * NND * HID / 4; i += 256) dst[i] = src[i];
        if (tid < 128) ((float4*)av)[tid] = ((const float4*)a2)[tid];
        if (tid < 49) sadj[tid] = adj[tid];
    }
    __syncthreads();

    {
        const int w = tid >> 5, lane = tid & 31;
        for (int r = w; r < GB2 * NND; r += 8) {
            const float* hr = hs + r * HID;
            float si = 0.f, sj = 0.f;
#pragma unroll
            for (int k = lane; k < HID; k += 32) {
                const float hv = hr[k];
                si = fmaf(hv, av[k], si);
                sj = fmaf(hv, av[HID + k], sj);
            }
#pragma unroll
            for (int off = 16; off > 0; off >>= 1) {
                si += __shfl_xor_sync(0xffffffffu, si, off);
                sj += __shfl_xor_sync(0xffffffffu, sj, off);
            }
            if (lane == 0) { ssi[r] = si; ssj[r] = sj; }
        }
    }
    __syncthreads();

    if (tid < GB2 * NND) {
        const int b = tid / 7, i = tid - b * 7;
        float e[7]; float mx = -3.0e38f;
#pragma unroll
        for (int j = 0; j < 7; ++j) {
            float v = ssi[b * 7 + i] + ssj[b * 7 + j];
            v = (v > 0.f) ? v : 0.2f * v;
            if (sadj[i * 7 + j] == 0.f) v = -3.0e38f;
            e[j] = v; mx = fmaxf(mx, v);
        }
        float s = 0.f;
#pragma unroll
        for (int j = 0; j < 7; ++j) {
            const float ex = (e[j] < -1.0e38f) ? 0.f : __expf(e[j] - mx);
            e[j] = ex; s += ex;
        }
        const float inv = 1.f / s;
        float* oa = out + (size_t)6 * BATCH + (size_t)(b0 + b) * 49 + i * 7;
#pragma unroll
        for (int j = 0; j < 7; ++j) {
            const float al = e[j] * inv;
            sal[tid * 7 + j] = al;
            oa[j] = al;
        }
    }
    __syncthreads();

    for (int idx = tid; idx < GB2 * NND * HID; idx += 256) {
        const int b = idx / (NND * HID);
        const int rem = idx - b * (NND * HID);
        const int i = rem >> 8;
        const float* al = sal + (b * 7 + i) * 7;
        const int d = rem & 255;
        float acc = 0.f;
#pragma unroll
        for (int j = 0; j < 7; ++j) acc = fmaf(al[j], hs[(b * 7 + j) * HID + d], acc);
        comb[b * CS + rem] = fmaxf(acc, 0.f);
    }
    for (int idx = tid; idx < GB2 * CTXD; idx += 256) {
        const int b = idx >> 8, c = idx & 255;
        comb[b * CS + NND * HID + c] = context[(size_t)(b0 + b) * CTXD + c];
    }
    __syncthreads();

    if (tid < 128) {            // weight head L1: 32 rows x 4 batches
        const int row = tid >> 2, b = tid & 3;
        const float4* wv = (const float4*)wh1_w + row * 512;
        const float4* cv = (const float4*)(comb + b * CS);
        float4 a4 = make_float4(0.f, 0.f, 0.f, 0.f);
        for (int k = 0; k < 512; ++k) {
            const float4 w4 = wv[k], c4 = cv[k];
            a4.x = fmaf(w4.x, c4.x, a4.x);
            a4.y = fmaf(w4.y, c4.y, a4.y);
            a4.z = fmaf(w4.z, c4.z, a4.z);
            a4.w = fmaf(w4.w, c4.w, a4.w);
        }
        t1s[b * 32 + row] = fmaxf(a4.x + a4.y + a4.z + a4.w + wh1_b[row], 0.f);
    } else if (tid < 192) {     // residual head L1: 16 rows x 4 batches
        const int t = tid - 128;
        const int row = t >> 2, b = t & 3;
        const float4* wv = (const float4*)rh1_w + row * 512;
        const float4* cv = (const float4*)(comb + b * CS);
        float4 a4 = make_float4(0.f, 0.f, 0.f, 0.f);
        for (int k = 0; k < 512; ++k) {
            const float4 w4 = wv[k], c4 = cv[k];
            a4.x = fmaf(w4.x, c4.x, a4.x);
            a4.y = fmaf(w4.y, c4.y, a4.y);
            a4.z = fmaf(w4.z, c4.z, a4.z);
            a4.w = fmaf(w4.w, c4.w, a4.w);
        }
        rrs[b * 16 + row] = tanhf(a4.x + a4.y + a4.z + a4.w + rh1_b[row]);
    }
    __syncthreads();

    if (tid < GB2) {
        const int b = tid;
        float t2[16];
#pragma unroll
        for (int o = 0; o < 16; ++o) {
            float s = wh2_b[o];
#pragma unroll
            for (int k = 0; k < 32; ++k) s = fmaf(t1s[b * 32 + k], wh2_w[o * 32 + k], s);
            t2[o] = fmaxf(s, 0.f);
        }
        float raw[5]; float mx = -3.0e38f;
#pragma unroll
        for (int o = 0; o < 5; ++o) {
            float s = wh3_b[o];
#pragma unroll
            for (int k = 0; k < 16; ++k) s = fmaf(t2[k], wh3_w[o * 16 + k], s);
            raw[o] = s; mx = fmaxf(mx, s);
        }
        float se = 0.f;
#pragma unroll
        for (int o = 0; o < 5; ++o) { raw[o] = __expf(raw[o] - mx); se += raw[o]; }
        const float inv = 1.f / se;
        float wp = 0.f;
#pragma unroll
        for (int o = 0; o < 5; ++o) {
            const float wt = raw[o] * inv;
            out[BATCH + (size_t)(b0 + b) * 5 + o] = wt;
            wp = fmaf(wt, base_preds[(size_t)(b0 + b) * 5 + o], wp);
        }
        float rr = rh2_b[0];
#pragma unroll
        for (int k = 0; k < 16; ++k) rr = fmaf(rrs[b * 16 + k], rh2_w[k], rr);
        out[b0 + b] = fmaxf(wp + rr * 0.05f, 0.05f);
    }
}

// ---------------------------------------------------------------------------
extern "C" void kernel_launch(void* const* d_in, const int* in_sizes, int n_in,
                              void* d_out, int out_size) {
    const float* node_feats = (const float*)d_in[0];
    const float* adj        = (const float*)d_in[1];
    const float* context    = (const float*)d_in[2];
    const float* base_preds = (const float*)d_in[3];
    const float* W1    = (const float*)d_in[4];
    const float* a1    = (const float*)d_in[5];
    const float* W2    = (const float*)d_in[6];
    const float* a2    = (const float*)d_in[7];
    const float* wh1_w = (const float*)d_in[8];
    const float* wh1_b = (const float*)d_in[9];
    const float* wh2_w = (const float*)d_in[10];
    const float* wh2_b = (const float*)d_in[11];
    const float* wh3_w = (const float*)d_in[12];
    const float* wh3_b = (const float*)d_in[13];
    const float* rh1_w = (const float*)d_in[14];
    const float* rh1_b = (const float*)d_in[15];
    const float* rh2_w = (const float*)d_in[16];
    const float* rh2_b = (const float*)d_in[17];
    float* out = (float*)d_out;

    float *h1p, *x2p, *h2p;
    __nv_bfloat16 *w1h, *w1l, *w2h, *w2l;
    cudaGetSymbolAddress((void**)&h1p, g_h1);
    cudaGetSymbolAddress((void**)&x2p, g_x2);
    cudaGetSymbolAddress((void**)&h2p, g_h2);
    cudaGetSymbolAddress((void**)&w1h, g_w1hi);
    cudaGetSymbolAddress((void**)&w1l, g_w1lo);
    cudaGetSymbolAddress((void**)&w2h, g_w2hi);
    cudaGetSymbolAddress((void**)&w2l, g_w2lo);

    const int smem1 = 15401 * 4;
    const int smem2 = 16381 * 4;
    cudaFuncSetAttribute(gemm_mma, cudaFuncAttributeMaxDynamicSharedMemorySize, G_SMEM);
    cudaFuncSetAttribute(attn1_kernel, cudaFuncAttributeMaxDynamicSharedMemorySize, smem1);
    cudaFuncSetAttribute(attn2_heads_kernel, cudaFuncAttributeMaxDynamicSharedMemorySize, smem2);

    // pre-split weights to bf16 hi/lo
    convw_kernel<<<(HID * FEATD + 255) / 256, 256>>>(W1, w1h, w1l, HID * FEATD);
    convw_kernel<<<(HID * HID + 255) / 256, 256>>>(W2, w2h, w2l, HID * HID);

    // h1 = node_feats @ W1^T      (HMMA, 3-term bf16 split)
    gemm_mma<<<dim3(MROWS / 128, 2), 256, G_SMEM>>>(node_feats, w1h, w1l, h1p, FEATD);
    // x2 = relu(alpha1 @ h1)
    attn1_kernel<<<BATCH / GB, 256, smem1>>>(h1p, adj, a1, x2p);
    // h2 = x2 @ W2^T
    gemm_mma<<<dim3(MROWS / 128, 2), 256, G_SMEM>>>(x2p, w2h, w2l, h2p, HID);
    // layer-2 attention + heads + outputs
    attn2_heads_kernel<<<BATCH / GB2, 256, smem2>>>(h2p, adj, a2, context, base_preds,
                                                    wh1_w, wh1_b, wh2_w, wh2_b,
                                                    wh3_w, wh3_b, rh1_w, rh1_b,
                                                    rh2_w, rh2_b, out);
}

// round 8
// speedup vs baseline: 1.7599x; 1.0165x over previous
#include <cuda_runtime.h>
#include <cuda_bf16.h>
#include <cstdint>
#include <cstddef>

#define BATCH 16384
#define NND   7
#define FEATD 512
#define HID   256
#define CTXD  256
#define MROWS (BATCH * NND)        // 114688
#define GB    8                    // batches per attn1 block
#define GB2   4                    // batches per attn2 block
#define CS    2052                 // padded combined stride (floats)

// smem staging layout for mma GEMM (bytes); row stride 80 = 5x16B -> LDSM
// row fetches for 8 consecutive rows land on 8 distinct 16B chunks (mod 128).
#define STR     80
#define AH_OFF  0
#define AL_OFF  10240
#define BH_OFF  20480
#define BL_OFF  30720
#define STAGE   40960
#define G_SMEM  (2 * STAGE)

// ---------------- scratch (no allocs allowed; __device__ globals) ----------
__device__ float g_h1[(size_t)MROWS * HID];
__device__ float g_x2[(size_t)MROWS * HID];
__device__ float g_h2[(size_t)MROWS * HID];
__device__ __nv_bfloat16 g_w1hi[HID * FEATD], g_w1lo[HID * FEATD];
__device__ __nv_bfloat16 g_w2hi[HID * HID],  g_w2lo[HID * HID];

// ---------------- helpers --------------------------------------------------
__device__ __forceinline__ uint32_t smem_u32(const void* p) {
    uint32_t a;
    asm("{ .reg .u64 t; cvta.to.shared.u64 t, %1; cvt.u32.u64 %0, t; }" : "=r"(a) : "l"(p));
    return a;
}
__device__ __forceinline__ void ldsm4(uint32_t* r, uint32_t addr) {
    asm volatile("ldmatrix.sync.aligned.m8n8.x4.shared.b16 {%0,%1,%2,%3}, [%4];"
                 : "=r"(r[0]), "=r"(r[1]), "=r"(r[2]), "=r"(r[3]) : "r"(addr));
}
__device__ __forceinline__ void mma_bf16(float* c, const uint32_t* a, const uint32_t* b) {
    asm volatile(
        "mma.sync.aligned.m16n8k16.row.col.f32.bf16.bf16.f32 "
        "{%0,%1,%2,%3}, {%4,%5,%6,%7}, {%8,%9}, {%0,%1,%2,%3};"
        : "+f"(c[0]), "+f"(c[1]), "+f"(c[2]), "+f"(c[3])
        : "r"(a[0]), "r"(a[1]), "r"(a[2]), "r"(a[3]), "r"(b[0]), "r"(b[1]));
}
__device__ __forceinline__ void cvt_hilo(float4 v, uint32_t& h0, uint32_t& h1,
                                         uint32_t& l0, uint32_t& l1) {
    __nv_bfloat162 ha = __float22bfloat162_rn(make_float2(v.x, v.y));
    __nv_bfloat162 hb = __float22bfloat162_rn(make_float2(v.z, v.w));
    float2 fa = __bfloat1622float2(ha);
    float2 fb = __bfloat1622float2(hb);
    __nv_bfloat162 la = __float22bfloat162_rn(make_float2(v.x - fa.x, v.y - fa.y));
    __nv_bfloat162 lb = __float22bfloat162_rn(make_float2(v.z - fb.x, v.w - fb.y));
    h0 = *(uint32_t*)&ha; h1 = *(uint32_t*)&hb;
    l0 = *(uint32_t*)&la; l1 = *(uint32_t*)&lb;
}

// ---------------------------------------------------------------------------
// Weight pre-split: fp32 -> bf16 hi + bf16 lo(residual)
// ---------------------------------------------------------------------------
__global__ void convw_kernel(const float* __restrict__ W, __nv_bfloat16* __restrict__ hi,
                             __nv_bfloat16* __restrict__ lo, int n) {
    int i = blockIdx.x * 256 + threadIdx.x;
    if (i < n) {
        float x = W[i];
        __nv_bfloat16 h = __float2bfloat16(x);
        hi[i] = h;
        lo[i] = __float2bfloat16(x - __bfloat162float(h));
    }
}

// ---------------------------------------------------------------------------
// HMMA GEMM: C[m,n] = sum_k A[m,k]*W[n,k].  A fp32 (M x K), W pre-split bf16
// hi/lo (256 x K). 3-term split: Ah*Bh + Al*Bh + Ah*Bl, issued TERM-MAJOR so
// each accumulator's reuse distance is 16 independent MMAs (breaks RAW chain).
// Block 128x128, BK=32, 256 threads = 8 warps (4 m x 2 n), warp tile 32x64.
// ---------------------------------------------------------------------------
__global__ void __launch_bounds__(256, 1)
gemm_mma(const float* __restrict__ A, const __nv_bfloat16* __restrict__ Bhi,
         const __nv_bfloat16* __restrict__ Blo, float* __restrict__ C, int K) {
    extern __shared__ char smem[];
    const uint32_t sb = smem_u32(smem);
    const int tid  = threadIdx.x;
    const int lane = tid & 31;
    const int wid  = tid >> 5;
    const int wm   = wid & 3;      // warp row block (32 rows)
    const int wn   = wid >> 2;     // warp col block (64 cols)
    const int m0   = blockIdx.x * 128;
    const int n0   = blockIdx.y * 128;
    const int nk   = K >> 5;       // BK = 32

    // --- staging maps ---
    const int ra = tid >> 1;                 // A row 0..127
    const int ca = (tid & 1) * 16;           // A col base (fp32 within 32-chunk)
    const float* Ag = A + (size_t)(m0 + ra) * K + ca;
    const int rb = tid >> 1;                 // B row 0..127
    const int cb = (tid & 1) * 2;            // B 16B chunk base (0 or 2)
    const char* Bhg = (const char*)Bhi + (size_t)(n0 + rb) * K * 2;
    const char* Blg = (const char*)Blo + (size_t)(n0 + rb) * K * 2;
    char* sA  = smem + AH_OFF + ra * STR + ca * 2;
    char* sAl = smem + AL_OFF + ra * STR + ca * 2;
    char* sBh = smem + BH_OFF + rb * STR + cb * 16;
    char* sBl = smem + BL_OFF + rb * STR + cb * 16;

    // --- LDSM address bases (per warp lane) ---
    const uint32_t a_off = AH_OFF + (uint32_t)(wm * 32 + (lane & 15)) * STR + ((lane >> 4) << 4);
    const uint32_t b_off = BH_OFF + (uint32_t)(wn * 64 + (lane & 7) + ((lane >> 4) << 3)) * STR
                         + ((lane & 8) << 1);

    float acc[2][8][4];
#pragma unroll
    for (int i = 0; i < 2; ++i)
#pragma unroll
        for (int j = 0; j < 8; ++j)
#pragma unroll
            for (int q = 0; q < 4; ++q) acc[i][j][q] = 0.f;

    float4 av[4];
    uint4  bhv[2], blv[2];

    // prologue: load + stage chunk 0
#pragma unroll
    for (int i = 0; i < 4; ++i) av[i] = *(const float4*)(Ag + i * 4);
#pragma unroll
    for (int j = 0; j < 2; ++j) {
        bhv[j] = *(const uint4*)(Bhg + (cb + j) * 16);
        blv[j] = *(const uint4*)(Blg + (cb + j) * 16);
    }
#pragma unroll
    for (int i = 0; i < 4; ++i) {
        uint32_t h0, h1, l0, l1;
        cvt_hilo(av[i], h0, h1, l0, l1);
        *(uint2*)(sA  + i * 8) = make_uint2(h0, h1);
        *(uint2*)(sAl + i * 8) = make_uint2(l0, l1);
    }
#pragma unroll
    for (int j = 0; j < 2; ++j) {
        *(uint4*)(sBh + j * 16) = bhv[j];
        *(uint4*)(sBl + j * 16) = blv[j];
    }
    __syncthreads();

    for (int kt = 0; kt < nk; ++kt) {
        const uint32_t bufo = (kt & 1) * STAGE;
        const bool more = (kt + 1 < nk);
        if (more) {
#pragma unroll
            for (int i = 0; i < 4; ++i) av[i] = *(const float4*)(Ag + (kt + 1) * 32 + i * 4);
#pragma unroll
            for (int j = 0; j < 2; ++j) {
                bhv[j] = *(const uint4*)(Bhg + (kt + 1) * 64 + (cb + j) * 16);
                blv[j] = *(const uint4*)(Blg + (kt + 1) * 64 + (cb + j) * 16);
            }
        }

        // ---- compute BK=32 from buffer bufo, term-major ----
#pragma unroll
        for (int ks = 0; ks < 2; ++ks) {
            const uint32_t ab = sb + bufo + a_off + ks * 32;
            const uint32_t bb = sb + bufo + b_off + ks * 32;
            uint32_t ah[2][4], al[2][4], bh[4][4], bl[4][4];
            ldsm4(ah[0], ab);
            ldsm4(ah[1], ab + 16 * STR);
            ldsm4(al[0], ab + (AL_OFF - AH_OFF));
            ldsm4(al[1], ab + (AL_OFF - AH_OFF) + 16 * STR);
#pragma unroll
            for (int p = 0; p < 4; ++p) {
                ldsm4(bh[p], bb + p * (16 * STR));
                ldsm4(bl[p], bb + p * (16 * STR) + (BL_OFF - BH_OFF));
            }
            // term 1: Ah * Bh   (16 independent MMAs)
#pragma unroll
            for (int p = 0; p < 4; ++p)
#pragma unroll
                for (int mi = 0; mi < 2; ++mi) {
                    mma_bf16(acc[mi][2 * p],     ah[mi], bh[p]);
                    mma_bf16(acc[mi][2 * p + 1], ah[mi], bh[p] + 2);
                }
            // term 2: Al * Bh
#pragma unroll
            for (int p = 0; p < 4; ++p)
#pragma unroll
                for (int mi = 0; mi < 2; ++mi) {
                    mma_bf16(acc[mi][2 * p],     al[mi], bh[p]);
                    mma_bf16(acc[mi][2 * p + 1], al[mi], bh[p] + 2);
                }
            // term 3: Ah * Bl
#pragma unroll
            for (int p = 0; p < 4; ++p)
#pragma unroll
                for (int mi = 0; mi < 2; ++mi) {
                    mma_bf16(acc[mi][2 * p],     ah[mi], bl[p]);
                    mma_bf16(acc[mi][2 * p + 1], ah[mi], bl[p] + 2);
                }
        }

        if (more) {
            char* dA  = smem + ((kt + 1) & 1) * STAGE;
#pragma unroll
            for (int i = 0; i < 4; ++i) {
                uint32_t h0, h1, l0, l1;
                cvt_hilo(av[i], h0, h1, l0, l1);
                *(uint2*)(dA + AH_OFF + ra * STR + ca * 2 + i * 8) = make_uint2(h0, h1);
                *(uint2*)(dA + AL_OFF + ra * STR + ca * 2 + i * 8) = make_uint2(l0, l1);
            }
#pragma unroll
            for (int j = 0; j < 2; ++j) {
                *(uint4*)(dA + BH_OFF + rb * STR + (cb + j) * 16) = bhv[j];
                *(uint4*)(dA + BL_OFF + rb * STR + (cb + j) * 16) = blv[j];
            }
            __syncthreads();
        }
    }

    // ---- epilogue ----
    const int g  = lane >> 2;
    const int cq = (lane & 3) * 2;
#pragma unroll
    for (int mi = 0; mi < 2; ++mi) {
        const int row0 = m0 + wm * 32 + mi * 16 + g;
        float* C0 = C + (size_t)row0 * 256 + n0 + wn * 64;
        float* C1 = C0 + (size_t)8 * 256;
#pragma unroll
        for (int ni = 0; ni < 8; ++ni) {
            *(float2*)(C0 + ni * 8 + cq) = make_float2(acc[mi][ni][0], acc[mi][ni][1]);
            *(float2*)(C1 + ni * 8 + cq) = make_float2(acc[mi][ni][2], acc[mi][ni][3]);
        }
    }
}

// ---------------------------------------------------------------------------
// GAT attention layer 1: x2 = relu(alpha1 @ h1). 8 batches / block.
// Warp w owns graph b=w: dots, then float4 aggregation with alphas in regs.
// ---------------------------------------------------------------------------
__global__ void __launch_bounds__(256)
attn1_kernel(const float* __restrict__ h1, const float* __restrict__ adj,
             const float* __restrict__ a1, float* __restrict__ x2) {
    extern __shared__ float sm[];
    float* hs   = sm;           // 14336
    float* av   = sm + 14336;   // 512
    float* sadj = sm + 14848;   // 49
    float* ssi  = sm + 14897;   // 56
    float* ssj  = sm + 14953;   // 56
    float* sal  = sm + 15009;   // 392
    const int tid = threadIdx.x;
    const int w = tid >> 5, lane = tid & 31;
    const size_t base = (size_t)blockIdx.x * (GB * NND * HID);

    {
        const float4* src = (const float4*)(h1 + base);
        float4* dst = (float4*)hs;
        for (int i = tid; i < GB * NND * HID / 4; i += 256) dst[i] = src[i];
        if (tid < 128) ((float4*)av)[tid] = ((const float4*)a1)[tid];
        if (tid < 49) sadj[tid] = adj[tid];
    }
    __syncthreads();

    {
#pragma unroll
        for (int ri = 0; ri < 7; ++ri) {
            const int r = w * 7 + ri;
            const float* hr = hs + r * HID;
            float si = 0.f, sj = 0.f;
#pragma unroll
            for (int k = lane; k < HID; k += 32) {
                const float hv = hr[k];
                si = fmaf(hv, av[k], si);
                sj = fmaf(hv, av[HID + k], sj);
            }
#pragma unroll
            for (int off = 16; off > 0; off >>= 1) {
                si += __shfl_xor_sync(0xffffffffu, si, off);
                sj += __shfl_xor_sync(0xffffffffu, sj, off);
            }
            if (lane == 0) { ssi[r] = si; ssj[r] = sj; }
        }
    }
    __syncthreads();

    if (tid < GB * NND) {
        const int b = tid / 7, i = tid - b * 7;
        float e[7]; float mx = -3.0e38f;
#pragma unroll
        for (int j = 0; j < 7; ++j) {
            float v = ssi[b * 7 + i] + ssj[b * 7 + j];
            v = (v > 0.f) ? v : 0.2f * v;
            if (sadj[i * 7 + j] == 0.f) v = -3.0e38f;
            e[j] = v; mx = fmaxf(mx, v);
        }
        float s = 0.f;
#pragma unroll
        for (int j = 0; j < 7; ++j) {
            const float ex = (e[j] < -1.0e38f) ? 0.f : __expf(e[j] - mx);
            e[j] = ex; s += ex;
        }
        const float inv = 1.f / s;
#pragma unroll
        for (int j = 0; j < 7; ++j) sal[tid * 7 + j] = e[j] * inv;
    }
    __syncthreads();

    // aggregation: warp w -> graph w, rows w*7..w*7+6, float4 over HID
    {
        const float* hb = hs + w * 7 * HID;
#pragma unroll
        for (int ri = 0; ri < 7; ++ri) {
            const int r = w * 7 + ri;
            const float* alr = sal + r * 7;
            float a0 = alr[0], a1v = alr[1], a2v = alr[2], a3 = alr[3],
                  a4 = alr[4], a5 = alr[5], a6 = alr[6];
#pragma unroll
            for (int d4 = lane; d4 < 64; d4 += 32) {
                const float4* p0 = (const float4*)(hb) + d4;
                float4 h0 = p0[0],  h1v = p0[64],  h2 = p0[128], h3 = p0[192],
                       h4 = p0[256], h5 = p0[320], h6 = p0[384];
                float4 o;
                o.x = a0*h0.x + a1v*h1v.x + a2v*h2.x + a3*h3.x + a4*h4.x + a5*h5.x + a6*h6.x;
                o.y = a0*h0.y + a1v*h1v.y + a2v*h2.y + a3*h3.y + a4*h4.y + a5*h5.y + a6*h6.y;
                o.z = a0*h0.z + a1v*h1v.z + a2v*h2.z + a3*h3.z + a4*h4.z + a5*h5.z + a6*h6.z;
                o.w = a0*h0.w + a1v*h1v.w + a2v*h2.w + a3*h3.w + a4*h4.w + a5*h5.w + a6*h6.w;
                o.x = fmaxf(o.x, 0.f); o.y = fmaxf(o.y, 0.f);
                o.z = fmaxf(o.z, 0.f); o.w = fmaxf(o.w, 0.f);
                *(float4*)(x2 + base + r * HID + d4 * 4) = o;
            }
        }
    }
}

// ---------------------------------------------------------------------------
// GAT layer 2 attention + MLP heads, fused. GB2=4 batches/block.
// out = [pred(B) | weights(B*5) | attn2(B*49)]
// ---------------------------------------------------------------------------
__global__ void __launch_bounds__(256)
attn2_heads_kernel(const float* __restrict__ h2, const float* __restrict__ adj,
                   const float* __restrict__ a2, const float* __restrict__ context,
                   const float* __restrict__ base_preds,
                   const float* __restrict__ wh1_w, const float* __restrict__ wh1_b,
                   const float* __restrict__ wh2_w, const float* __restrict__ wh2_b,
                   const float* __restrict__ wh3_w, const float* __restrict__ wh3_b,
                   const float* __restrict__ rh1_w, const float* __restrict__ rh1_b,
                   const float* __restrict__ rh2_w, const float* __restrict__ rh2_b,
                   float* __restrict__ out) {
    extern __shared__ float sm[];
    float* hs   = sm;            // 7168
    float* comb = sm + 7168;     // 4*2052 = 8208
    float* av   = sm + 15376;    // 512
    float* sadj = sm + 15888;    // 49
    float* ssi  = sm + 15937;    // 28
    float* ssj  = sm + 15965;    // 28
    float* sal  = sm + 15993;    // 196
    float* t1s  = sm + 16189;    // 128
    float* rrs  = sm + 16317;    // 64   (total 16381 floats)
    const int tid = threadIdx.x;
    const int w = tid >> 5, lane = tid & 31;
    const int b0 = blockIdx.x * GB2;
    const size_t base = (size_t)blockIdx.x * (GB2 * NND * HID);

    {
        const float4* src = (const float4*)(h2 + base);
        float4* dst = (float4*)hs;
        for (int i = tid; i < GB2 * NND * HID / 4; i += 256) dst[i] = src[i];
        if (tid < 128) ((float4*)av)[tid] = ((const float4*)a2)[tid];
        if (tid < 49) sadj[tid] = adj[tid];
    }
    __syncthreads();

    {
        for (int r = w; r < GB2 * NND; r += 8) {
            const float* hr = hs + r * HID;
            float si = 0.f, sj = 0.f;
#pragma unroll
            for (int k = lane; k < HID; k += 32) {
                const float hv = hr[k];
                si = fmaf(hv, av[k], si);
                sj = fmaf(hv, av[HID + k], sj);
            }
#pragma unroll
            for (int off = 16; off > 0; off >>= 1) {
                si += __shfl_xor_sync(0xffffffffu, si, off);
                sj += __shfl_xor_sync(0xffffffffu, sj, off);
            }
            if (lane == 0) { ssi[r] = si; ssj[r] = sj; }
        }
    }
    __syncthreads();

    if (tid < GB2 * NND) {
        const int b = tid / 7, i = tid - b * 7;
        float e[7]; float mx = -3.0e38f;
#pragma unroll
        for (int j = 0; j < 7; ++j) {
            float v = ssi[b * 7 + i] + ssj[b * 7 + j];
            v = (v > 0.f) ? v : 0.2f * v;
            if (sadj[i * 7 + j] == 0.f) v = -3.0e38f;
            e[j] = v; mx = fmaxf(mx, v);
        }
        float s = 0.f;
#pragma unroll
        for (int j = 0; j < 7; ++j) {
            const float ex = (e[j] < -1.0e38f) ? 0.f : __expf(e[j] - mx);
            e[j] = ex; s += ex;
        }
        const float inv = 1.f / s;
        float* oa = out + (size_t)6 * BATCH + (size_t)(b0 + b) * 49 + i * 7;
#pragma unroll
        for (int j = 0; j < 7; ++j) {
            const float al = e[j] * inv;
            sal[tid * 7 + j] = al;
            oa[j] = al;
        }
    }
    __syncthreads();

    // aggregation: warp handles rows r = w, w+8, ... (28 rows over 8 warps)
    for (int r = w; r < GB2 * NND; r += 8) {
        const int b = r / 7;
        const float* hb = hs + b * 7 * HID;
        const float* alr = sal + r * 7;
        float a0 = alr[0], a1v = alr[1], a2v = alr[2], a3 = alr[3],
              a4 = alr[4], a5 = alr[5], a6 = alr[6];
        const int rem = r - b * 7;
#pragma unroll
        for (int d4 = lane; d4 < 64; d4 += 32) {
            const float4* p0 = (const float4*)(hb) + d4;
            float4 h0 = p0[0],  h1v = p0[64],  h2 = p0[128], h3 = p0[192],
                   h4 = p0[256], h5 = p0[320], h6 = p0[384];
            float4 o;
            o.x = a0*h0.x + a1v*h1v.x + a2v*h2.x + a3*h3.x + a4*h4.x + a5*h5.x + a6*h6.x;
            o.y = a0*h0.y + a1v*h1v.y + a2v*h2.y + a3*h3.y + a4*h4.y + a5*h5.y + a6*h6.y;
            o.z = a0*h0.z + a1v*h1v.z + a2v*h2.z + a3*h3.z + a4*h4.z + a5*h5.z + a6*h6.z;
            o.w = a0*h0.w + a1v*h1v.w + a2v*h2.w + a3*h3.w + a4*h4.w + a5*h5.w + a6*h6.w;
            o.x = fmaxf(o.x, 0.f); o.y = fmaxf(o.y, 0.f);
            o.z = fmaxf(o.z, 0.f); o.w = fmaxf(o.w, 0.f);
            *(float4*)(comb + b * CS + rem * HID + d4 * 4) = o;
        }
    }
    for (int idx = tid; idx < GB2 * CTXD; idx += 256) {
        const int b = idx >> 8, c = idx & 255;
        comb[b * CS + NND * HID + c] = context[(size_t)(b0 + b) * CTXD + c];
    }
    __syncthreads();

    if (tid < 128) {            // weight head L1: 32 rows x 4 batches
        const int row = tid >> 2, b = tid & 3;
        const float4* wv = (const float4*)wh1_w + row * 512;
        const float4* cv = (const float4*)(comb + b * CS);
        float4 a4 = make_float4(0.f, 0.f, 0.f, 0.f);
        for (int k = 0; k < 512; ++k) {
            const float4 w4 = wv[k], c4 = cv[k];
            a4.x = fmaf(w4.x, c4.x, a4.x);
            a4.y = fmaf(w4.y, c4.y, a4.y);
            a4.z = fmaf(w4.z, c4.z, a4.z);
            a4.w = fmaf(w4.w, c4.w, a4.w);
        }
        t1s[b * 32 + row] = fmaxf(a4.x + a4.y + a4.z + a4.w + wh1_b[row], 0.f);
    } else if (tid < 192) {     // residual head L1: 16 rows x 4 batches
        const int t = tid - 128;
        const int row = t >> 2, b = t & 3;
        const float4* wv = (const float4*)rh1_w + row * 512;
        const float4* cv = (const float4*)(comb + b * CS);
        float4 a4 = make_float4(0.f, 0.f, 0.f, 0.f);
        for (int k = 0; k < 512; ++k) {
            const float4 w4 = wv[k], c4 = cv[k];
            a4.x = fmaf(w4.x, c4.x, a4.x);
            a4.y = fmaf(w4.y, c4.y, a4.y);
            a4.z = fmaf(w4.z, c4.z, a4.z);
            a4.w = fmaf(w4.w, c4.w, a4.w);
        }
        rrs[b * 16 + row] = tanhf(a4.x + a4.y + a4.z + a4.w + rh1_b[row]);
    }
    __syncthreads();

    if (tid < GB2) {
        const int b = tid;
        float t2[16];
#pragma unroll
        for (int o = 0; o < 16; ++o) {
            float s = wh2_b[o];
#pragma unroll
            for (int k = 0; k < 32; ++k) s = fmaf(t1s[b * 32 + k], wh2_w[o * 32 + k], s);
            t2[o] = fmaxf(s, 0.f);
        }
        float raw[5]; float mx = -3.0e38f;
#pragma unroll
        for (int o = 0; o < 5; ++o) {
            float s = wh3_b[o];
#pragma unroll
            for (int k = 0; k < 16; ++k) s = fmaf(t2[k], wh3_w[o * 16 + k], s);
            raw[o] = s; mx = fmaxf(mx, s);
        }
        float se = 0.f;
#pragma unroll
        for (int o = 0; o < 5; ++o) { raw[o] = __expf(raw[o] - mx); se += raw[o]; }
        const float inv = 1.f / se;
        float wp = 0.f;
#pragma unroll
        for (int o = 0; o < 5; ++o) {
            const float wt = raw[o] * inv;
            out[BATCH + (size_t)(b0 + b) * 5 + o] = wt;
            wp = fmaf(wt, base_preds[(size_t)(b0 + b) * 5 + o], wp);
        }
        float rr = rh2_b[0];
#pragma unroll
        for (int k = 0; k < 16; ++k) rr = fmaf(rrs[b * 16 + k], rh2_w[k], rr);
        out[b0 + b] = fmaxf(wp + rr * 0.05f, 0.05f);
    }
}

// ---------------------------------------------------------------------------
extern "C" void kernel_launch(void* const* d_in, const int* in_sizes, int n_in,
                              void* d_out, int out_size) {
    const float* node_feats = (const float*)d_in[0];
    const float* adj        = (const float*)d_in[1];
    const float* context    = (const float*)d_in[2];
    const float* base_preds = (const float*)d_in[3];
    const float* W1    = (const float*)d_in[4];
    const float* a1    = (const float*)d_in[5];
    const float* W2    = (const float*)d_in[6];
    const float* a2    = (const float*)d_in[7];
    const float* wh1_w = (const float*)d_in[8];
    const float* wh1_b = (const float*)d_in[9];
    const float* wh2_w = (const float*)d_in[10];
    const float* wh2_b = (const float*)d_in[11];
    const float* wh3_w = (const float*)d_in[12];
    const float* wh3_b = (const float*)d_in[13];
    const float* rh1_w = (const float*)d_in[14];
    const float* rh1_b = (const float*)d_in[15];
    const float* rh2_w = (const float*)d_in[16];
    const float* rh2_b = (const float*)d_in[17];
    float* out = (float*)d_out;

    float *h1p, *x2p, *h2p;
    __nv_bfloat16 *w1h, *w1l, *w2h, *w2l;
    cudaGetSymbolAddress((void**)&h1p, g_h1);
    cudaGetSymbolAddress((void**)&x2p, g_x2);
    cudaGetSymbolAddress((void**)&h2p, g_h2);
    cudaGetSymbolAddress((void**)&w1h, g_w1hi);
    cudaGetSymbolAddress((void**)&w1l, g_w1lo);
    cudaGetSymbolAddress((void**)&w2h, g_w2hi);
    cudaGetSymbolAddress((void**)&w2l, g_w2lo);

    const int smem1 = 15401 * 4;
    const int smem2 = 16381 * 4;
    cudaFuncSetAttribute(gemm_mma, cudaFuncAttributeMaxDynamicSharedMemorySize, G_SMEM);
    cudaFuncSetAttribute(attn1_kernel, cudaFuncAttributeMaxDynamicSharedMemorySize, smem1);
    cudaFuncSetAttribute(attn2_heads_kernel, cudaFuncAttributeMaxDynamicSharedMemorySize, smem2);

    // pre-split weights to bf16 hi/lo
    convw_kernel<<<(HID * FEATD + 255) / 256, 256>>>(W1, w1h, w1l, HID * FEATD);
    convw_kernel<<<(HID * HID + 255) / 256, 256>>>(W2, w2h, w2l, HID * HID);

    // h1 = node_feats @ W1^T      (HMMA, 3-term bf16 split, term-major)
    gemm_mma<<<dim3(MROWS / 128, 2), 256, G_SMEM>>>(node_feats, w1h, w1l, h1p, FEATD);
    // x2 = relu(alpha1 @ h1)
    attn1_kernel<<<BATCH / GB, 256, smem1>>>(h1p, adj, a1, x2p);
    // h2 = x2 @ W2^T
    gemm_mma<<<dim3(MROWS / 128, 2), 256, G_SMEM>>>(x2p, w2h, w2l, h2p, HID);
    // layer-2 attention + heads + outputs
    attn2_heads_kernel<<<BATCH / GB2, 256, smem2>>>(h2p, adj, a2, context, base_preds,
                                                    wh1_w, wh1_b, wh2_w, wh2_b,
                                                    wh3_w, wh3_b, rh1_w, rh1_b,
                                                    rh2_w, rh2_b, out);
}